// round 11
// baseline (speedup 1.0000x reference)
#include <cuda_runtime.h>
#include <cuda_fp16.h>
#include <cstdint>

#define Bc 4
#define Nc 2048
#define Cc 256
#define Hc 8
#define DHc 32
#define SCALEF 0.17677669529663687f   // 32^-0.5
#define KSS 40                        // K stage row stride (halfs)
#define MSKS 20                       // mask stage row stride (floats)
#define CBS 34                        // combine row stride (floats, EVEN for float2)
#define PS  2056                      // P buffer row stride (halfs; 4r-word skew)

// ---- scratch (static device allocations) ----
__device__ __half g_qh [Bc*Hc*Nc*DHc];   // Q [bh][n][d], pre-scaled by SCALEF
__device__ __half g_kh [Bc*Hc*Nc*DHc];   // K [bh][n][d]
__device__ __half g_vth[Bc*Hc*DHc*Nc];   // V transposed [bh][d][n]
__device__ float  g_x  [Bc*Nc*Cc];       // attention output [B*N, C]
__device__ unsigned int g_rmaxb[Bc*Nc];  // max_k mask[b,k,q] as monotone uint bits

// ---- helpers ----
__device__ __forceinline__ float to_tf32(float x) {
    unsigned u;
    asm("cvt.rna.tf32.f32 %0, %1;" : "=r"(u) : "f"(x));
    return __uint_as_float(u);
}
__device__ __forceinline__ void mma8(float& d0, float& d1, float& d2, float& d3,
                                     unsigned a0, unsigned a1, unsigned a2, unsigned a3,
                                     unsigned b0, unsigned b1) {
    asm volatile(
        "mma.sync.aligned.m16n8k8.row.col.f32.tf32.tf32.f32 "
        "{%0,%1,%2,%3},{%4,%5,%6,%7},{%8,%9},{%0,%1,%2,%3};"
        : "+f"(d0), "+f"(d1), "+f"(d2), "+f"(d3)
        : "r"(a0), "r"(a1), "r"(a2), "r"(a3), "r"(b0), "r"(b1));
}
__device__ __forceinline__ void mma16(float& d0, float& d1, float& d2, float& d3,
                                      unsigned a0, unsigned a1, unsigned a2, unsigned a3,
                                      unsigned b0, unsigned b1) {
    asm volatile(
        "mma.sync.aligned.m16n8k16.row.col.f32.f16.f16.f32 "
        "{%0,%1,%2,%3},{%4,%5,%6,%7},{%8,%9},{%0,%1,%2,%3};"
        : "+f"(d0), "+f"(d1), "+f"(d2), "+f"(d3)
        : "r"(a0), "r"(a1), "r"(a2), "r"(a3), "r"(b0), "r"(b1));
}
__device__ __forceinline__ unsigned pack_h2(float lo, float hi) {
    __half2 h = __floats2half2_rn(lo, hi);
    return *(unsigned*)&h;
}
__device__ __forceinline__ unsigned sptr(const void* p) {
    return (unsigned)__cvta_generic_to_shared(p);
}
#define CP_ASYNC16(dst, src) \
    asm volatile("cp.async.cg.shared.global [%0], [%1], 16;" :: "r"(dst), "l"(src))
#define CP_COMMIT() asm volatile("cp.async.commit_group;")
#define CP_WAIT(n)  asm volatile("cp.async.wait_group %0;" :: "n"(n))

// ---------------------------------------------------------------------------
// Kernel 0: column-max of mask via atomicMax on float bits (mask > 0).
// ---------------------------------------------------------------------------
__global__ void __launch_bounds__(256) rmax_kernel(const float* __restrict__ mask)
{
    int q  = blockIdx.x * 256 + threadIdx.x;
    int k0 = blockIdx.y * 256;
    int b  = blockIdx.z;
    const float* mc = mask + (size_t)b * Nc * Nc + q;
    float mx = 0.f;
#pragma unroll 8
    for (int k = 0; k < 256; k++)
        mx = fmaxf(mx, mc[(size_t)(k0 + k) * Nc]);
    atomicMax(&g_rmaxb[b * Nc + q], __float_as_uint(mx));
}

// ---------------------------------------------------------------------------
// Kernel 1: QKV projection via tf32 MMA. Tile 32m x 64n, 8 warps.
// Writes half outputs: Q (pre-scaled), K row-major, V transposed.
// ---------------------------------------------------------------------------
__global__ void __launch_bounds__(256) qkv_mma_kernel(
    const float* __restrict__ X,
    const float* __restrict__ Wq, const float* __restrict__ Wk, const float* __restrict__ Wv,
    const float* __restrict__ bq, const float* __restrict__ bk, const float* __restrict__ bv)
{
    __shared__ float As[32][36];
    __shared__ float Bs[64][36];
    __shared__ float bias_s[64];

    const float* W; const float* bias;
    if (blockIdx.z == 0)      { W = Wq; bias = bq; }
    else if (blockIdx.z == 1) { W = Wk; bias = bk; }
    else                      { W = Wv; bias = bv; }

    int m0 = blockIdx.x * 32;
    int n0 = blockIdx.y * 64;
    int tid = threadIdx.x;
    int wid = tid >> 5, lane = tid & 31;
    int grp = lane >> 2, tig = lane & 3;
    int mw = wid >> 2, nw = wid & 3;

    if (tid < 64) bias_s[tid] = bias[n0 + tid];

    float acc[2][4];
#pragma unroll
    for (int i = 0; i < 2; i++)
#pragma unroll
        for (int j = 0; j < 4; j++) acc[i][j] = 0.f;

    int arow = tid >> 3, aseg = tid & 7;

    for (int c = 0; c < 8; c++) {
        float4 xa = *(const float4*)(X + (size_t)(m0 + arow) * Cc + c * 32 + aseg * 4);
        float4 wb0 = *(const float4*)(W + (size_t)(n0 + arow) * Cc + c * 32 + aseg * 4);
        float4 wb1 = *(const float4*)(W + (size_t)(n0 + 32 + arow) * Cc + c * 32 + aseg * 4);
        __syncthreads();
        xa.x = to_tf32(xa.x); xa.y = to_tf32(xa.y); xa.z = to_tf32(xa.z); xa.w = to_tf32(xa.w);
        *(float4*)&As[arow][aseg * 4] = xa;
        wb0.x = to_tf32(wb0.x); wb0.y = to_tf32(wb0.y); wb0.z = to_tf32(wb0.z); wb0.w = to_tf32(wb0.w);
        *(float4*)&Bs[arow][aseg * 4] = wb0;
        wb1.x = to_tf32(wb1.x); wb1.y = to_tf32(wb1.y); wb1.z = to_tf32(wb1.z); wb1.w = to_tf32(wb1.w);
        *(float4*)&Bs[32 + arow][aseg * 4] = wb1;
        __syncthreads();

#pragma unroll
        for (int s = 0; s < 4; s++) {
            unsigned a0 = __float_as_uint(As[mw * 16 + grp][s * 8 + tig]);
            unsigned a1 = __float_as_uint(As[mw * 16 + grp + 8][s * 8 + tig]);
            unsigned a2 = __float_as_uint(As[mw * 16 + grp][s * 8 + tig + 4]);
            unsigned a3 = __float_as_uint(As[mw * 16 + grp + 8][s * 8 + tig + 4]);
#pragma unroll
            for (int nt = 0; nt < 2; nt++) {
                unsigned b0 = __float_as_uint(Bs[nw * 16 + nt * 8 + grp][s * 8 + tig]);
                unsigned b1 = __float_as_uint(Bs[nw * 16 + nt * 8 + grp][s * 8 + tig + 4]);
                mma8(acc[nt][0], acc[nt][1], acc[nt][2], acc[nt][3], a0, a1, a2, a3, b0, b1);
            }
        }
    }

#pragma unroll
    for (int nt = 0; nt < 2; nt++) {
        int c0 = n0 + nw * 16 + nt * 8 + 2 * tig;
#pragma unroll
        for (int rr = 0; rr < 2; rr++) {
            int m = m0 + mw * 16 + grp + rr * 8;
            int b = m >> 11, nr = m & (Nc - 1);
            float v0 = acc[nt][rr * 2 + 0] + bias_s[c0 - n0];
            float v1 = acc[nt][rr * 2 + 1] + bias_s[c0 - n0 + 1];
            int h = c0 >> 5, d = c0 & 31;
            size_t bh = (size_t)(b * Hc + h);
            if (blockIdx.z == 0) {
                __half2 hv = __floats2half2_rn(v0 * SCALEF, v1 * SCALEF);
                *(__half2*)&g_qh[(bh * Nc + nr) * DHc + d] = hv;
            } else if (blockIdx.z == 1) {
                __half2 hv = __floats2half2_rn(v0, v1);
                *(__half2*)&g_kh[(bh * Nc + nr) * DHc + d] = hv;
            } else {
                g_vth[(bh * DHc + d) * Nc + nr]     = __float2half_rn(v0);
                g_vth[(bh * DHc + d + 1) * Nc + nr] = __float2half_rn(v1);
            }
        }
    }
}

// ---------------------------------------------------------------------------
// Kernel 2: attention. S register-resident; masked P spilled to a DEDICATED
// skewed smem buffer (Ph) as half — removes the ph[32] register pressure that
// forced local-memory spills at 512 threads. Phase-3 A-frags read back the
// exact addresses each lane wrote (no extra syncs, conflict-free banks).
// ---------------------------------------------------------------------------
__global__ void __launch_bounds__(512) attn_kernel(const float* __restrict__ mask,
                                                   float* __restrict__ vis)
{
    extern __shared__ float sm[];
    __half* Qsh = (__half*)sm;            // [16][KSS] halfs (320 floats)
    float*  St  = sm + 320;               // 20480-float union region
    __half* Ph  = (__half*)(sm + 320 + 20480);   // P buffer [16][PS] halfs
    float*  red = sm + 320 + 20480 + (16 * PS) / 2;  // [2][16*17]

    __half* Kb0h = (__half*)St;           // K buffers: 512 rows x KSS halfs
    __half* Kb1h = (__half*)St + 512 * KSS;
    float*  Mb0  = St;                    // mask buffers: 512 rows x MSKS floats
    float*  Mb1  = St + 512 * MSKS;
    float*  Comb = St;                    // phase-3 combine [16 w][16 rows][CBS]

    int h  = blockIdx.x;
    int q0 = blockIdx.y * 16;
    int b  = blockIdx.z;
    int bh = b * Hc + h;
    const __half* qhp  = g_qh  + (size_t)bh * Nc * DHc;
    const __half* khp  = g_kh  + (size_t)bh * Nc * DHc;
    const __half* vthp = g_vth + (size_t)bh * DHc * Nc;
    const float* mbase = mask + (size_t)b * Nc * Nc;

    int tid  = threadIdx.x;
    int wid  = tid >> 5;
    int lane = tid & 31;
    int grp  = lane >> 2;                 // 0..7
    int tig  = lane & 3;                  // 0..3

    // stage Q tile (512 halfs as 256 words)
    if (tid < 256) {
        int q = tid >> 4, dp = tid & 15;
        unsigned v = ((const unsigned*)qhp)[q0 * 16 + tid];
        *(unsigned*)&Qsh[q * KSS + dp * 2] = v;
    }

    // K stage prologue via cp.async (chunks 0,1)
    unsigned kb0 = sptr(Kb0h), kb1 = sptr(Kb1h);
    {
        const __half* s0 = khp + (size_t)tid * 32;
        unsigned d0 = kb0 + tid * (KSS * 2);
        CP_ASYNC16(d0, s0); CP_ASYNC16(d0 + 16, s0 + 8);
        CP_ASYNC16(d0 + 32, s0 + 16); CP_ASYNC16(d0 + 48, s0 + 24);
        CP_COMMIT();
        const __half* s1 = khp + (size_t)(512 + tid) * 32;
        unsigned d1 = kb1 + tid * (KSS * 2);
        CP_ASYNC16(d1, s1); CP_ASYNC16(d1 + 16, s1 + 8);
        CP_ASYNC16(d1 + 32, s1 + 16); CP_ASYNC16(d1 + 48, s1 + 24);
        CP_COMMIT();
    }
    __syncthreads();   // Qsh ready

    // Q A-fragments (shared by all warps): 2 k16 steps x 4 regs
    unsigned aq[2][4];
#pragma unroll
    for (int s = 0; s < 2; s++) {
        aq[s][0] = *(const unsigned*)&Qsh[grp * KSS + s * 16 + 2 * tig];
        aq[s][1] = *(const unsigned*)&Qsh[(grp + 8) * KSS + s * 16 + 2 * tig];
        aq[s][2] = *(const unsigned*)&Qsh[grp * KSS + s * 16 + 2 * tig + 8];
        aq[s][3] = *(const unsigned*)&Qsh[(grp + 8) * KSS + s * 16 + 2 * tig + 8];
    }

    // ---- Phase 1: S = Q K^T in registers. s[c*16 + nt*4 + i] ----
    float s[64];
#pragma unroll
    for (int c = 0; c < 4; c++) {
        if (c < 3) CP_WAIT(1); else CP_WAIT(0);
        __syncthreads();
        const __half* bb = (c & 1) ? Kb1h : Kb0h;
#pragma unroll
        for (int nt = 0; nt < 4; nt++) {
            int kb = wid * 32 + nt * 8;
            float d0 = 0.f, d1 = 0.f, d2 = 0.f, d3 = 0.f;
#pragma unroll
            for (int s2 = 0; s2 < 2; s2++) {
                unsigned b0 = *(const unsigned*)&bb[(kb + grp) * KSS + s2 * 16 + 2 * tig];
                unsigned b1 = *(const unsigned*)&bb[(kb + grp) * KSS + s2 * 16 + 2 * tig + 8];
                mma16(d0, d1, d2, d3, aq[s2][0], aq[s2][1], aq[s2][2], aq[s2][3], b0, b1);
            }
            s[c * 16 + nt * 4 + 0] = d0;
            s[c * 16 + nt * 4 + 1] = d1;
            s[c * 16 + nt * 4 + 2] = d2;
            s[c * 16 + nt * 4 + 3] = d3;
        }
        __syncthreads();
        if (c < 2) {   // stage chunk c+2 into the buffer just freed
            const __half* sn = khp + (size_t)((c + 2) * 512 + tid) * 32;
            unsigned dn = ((c & 1) ? kb1 : kb0) + tid * (KSS * 2);
            CP_ASYNC16(dn, sn); CP_ASYNC16(dn + 16, sn + 8);
            CP_ASYNC16(dn + 32, sn + 16); CP_ASYNC16(dn + 48, sn + 24);
            CP_COMMIT();
        }
    }

    // mask stage prologue (chunks 0,1) — overlaps the stats reduction below
    unsigned mb0 = sptr(Mb0), mb1 = sptr(Mb1);
    {
        const float* s0 = mbase + (size_t)tid * Nc + q0;
        unsigned d0 = mb0 + tid * (MSKS * 4);
        CP_ASYNC16(d0, s0); CP_ASYNC16(d0 + 16, s0 + 4);
        CP_ASYNC16(d0 + 32, s0 + 8); CP_ASYNC16(d0 + 48, s0 + 12);
        CP_COMMIT();
        const float* s1 = mbase + (size_t)(512 + tid) * Nc + q0;
        unsigned d1 = mb1 + tid * (MSKS * 4);
        CP_ASYNC16(d1, s1); CP_ASYNC16(d1 + 16, s1 + 4);
        CP_ASYNC16(d1 + 32, s1 + 8); CP_ASYNC16(d1 + 48, s1 + 12);
        CP_COMMIT();
    }

    // ---- softmax stats: quad shfl + [16][17] block reduce ----
    float mx0 = -1e30f, mx1 = -1e30f;
#pragma unroll
    for (int i = 0; i < 16; i++) {
        mx0 = fmaxf(mx0, fmaxf(s[i * 4 + 0], s[i * 4 + 1]));
        mx1 = fmaxf(mx1, fmaxf(s[i * 4 + 2], s[i * 4 + 3]));
    }
    mx0 = fmaxf(mx0, __shfl_xor_sync(0xffffffffu, mx0, 1));
    mx0 = fmaxf(mx0, __shfl_xor_sync(0xffffffffu, mx0, 2));
    mx1 = fmaxf(mx1, __shfl_xor_sync(0xffffffffu, mx1, 1));
    mx1 = fmaxf(mx1, __shfl_xor_sync(0xffffffffu, mx1, 2));
    if (tig == 0) {
        red[grp * 17 + wid]       = mx0;
        red[(8 + grp) * 17 + wid] = mx1;
    }
    __syncthreads();
    mx0 = -1e30f; mx1 = -1e30f;
#pragma unroll
    for (int w = 0; w < 16; w++) {
        mx0 = fmaxf(mx0, red[grp * 17 + w]);
        mx1 = fmaxf(mx1, red[(8 + grp) * 17 + w]);
    }

    float sum0 = 0.f, sum1 = 0.f;
#pragma unroll
    for (int i = 0; i < 16; i++) {
        float e0 = __expf(s[i * 4 + 0] - mx0);
        float e1 = __expf(s[i * 4 + 1] - mx0);
        float e2 = __expf(s[i * 4 + 2] - mx1);
        float e3 = __expf(s[i * 4 + 3] - mx1);
        s[i * 4 + 0] = e0; s[i * 4 + 1] = e1; s[i * 4 + 2] = e2; s[i * 4 + 3] = e3;
        sum0 += e0 + e1; sum1 += e2 + e3;
    }
    sum0 += __shfl_xor_sync(0xffffffffu, sum0, 1);
    sum0 += __shfl_xor_sync(0xffffffffu, sum0, 2);
    sum1 += __shfl_xor_sync(0xffffffffu, sum1, 1);
    sum1 += __shfl_xor_sync(0xffffffffu, sum1, 2);
    float* red2 = red + 272;
    if (tig == 0) {
        red2[grp * 17 + wid]       = sum0;
        red2[(8 + grp) * 17 + wid] = sum1;
    }
    __syncthreads();
    sum0 = 0.f; sum1 = 0.f;
#pragma unroll
    for (int w = 0; w < 16; w++) {
        sum0 += red2[grp * 17 + w];
        sum1 += red2[(8 + grp) * 17 + w];
    }
    float inv0 = 1.f / sum0, inv1 = 1.f / sum1;
    float rmx0 = 1.f / __uint_as_float(g_rmaxb[b * Nc + q0 + grp]);
    float rmx1 = 1.f / __uint_as_float(g_rmaxb[b * Nc + q0 + 8 + grp]);

    // ---- Phase 2: vis from regs + mask multiply; masked P -> Ph (smem) ----
    float* visrow0 = vis + ((size_t)bh * Nc + q0 + grp) * Nc;
    float* visrow1 = vis + ((size_t)bh * Nc + q0 + 8 + grp) * Nc;

#pragma unroll
    for (int ch = 0; ch < 4; ch++) {
        if (ch < 3) CP_WAIT(1); else CP_WAIT(0);
        __syncthreads();
        const float* Mb = (ch & 1) ? Mb1 : Mb0;
#pragma unroll
        for (int nt = 0; nt < 4; nt++) {
            int base = ch * 16 + nt * 4;
            int kk = wid * 32 + nt * 8 + 2 * tig;     // col within chunk
            int col = ch * 512 + kk;
            float p0 = s[base + 0] * inv0;
            float p1 = s[base + 1] * inv0;
            float p2 = s[base + 2] * inv1;
            float p3 = s[base + 3] * inv1;
            *(float2*)&visrow0[col] = make_float2(p0, p1);
            *(float2*)&visrow1[col] = make_float2(p2, p3);
            float m0a = Mb[kk * MSKS + grp];
            float m0b = Mb[(kk + 1) * MSKS + grp];
            float m1a = Mb[kk * MSKS + 8 + grp];
            float m1b = Mb[(kk + 1) * MSKS + 8 + grp];
            *(unsigned*)&Ph[grp * PS + col]       = pack_h2(p0 * m0a * rmx0, p1 * m0b * rmx0);
            *(unsigned*)&Ph[(8 + grp) * PS + col] = pack_h2(p2 * m1a * rmx1, p3 * m1b * rmx1);
        }
        __syncthreads();
        if (ch < 2) {   // stage mask chunk ch+2
            const float* sn = mbase + (size_t)((ch + 2) * 512 + tid) * Nc + q0;
            unsigned dn = ((ch & 1) ? mb1 : mb0) + tid * (MSKS * 4);
            CP_ASYNC16(dn, sn); CP_ASYNC16(dn + 16, sn + 4);
            CP_ASYNC16(dn + 32, sn + 8); CP_ASYNC16(dn + 48, sn + 12);
            CP_COMMIT();
        }
    }

    // ---- Phase 3: x = P V; A-frags from Ph (same lane wrote them) ----
    {
        float xac[4][4];
#pragma unroll
        for (int i = 0; i < 4; i++)
#pragma unroll
            for (int j = 0; j < 4; j++) xac[i][j] = 0.f;

#pragma unroll
        for (int c = 0; c < 4; c++) {
#pragma unroll
            for (int j = 0; j < 2; j++) {
                int k0 = c * 512 + wid * 32 + j * 16;
                unsigned a0 = *(const unsigned*)&Ph[grp * PS + k0 + 2 * tig];
                unsigned a1 = *(const unsigned*)&Ph[(8 + grp) * PS + k0 + 2 * tig];
                unsigned a2 = *(const unsigned*)&Ph[grp * PS + k0 + 2 * tig + 8];
                unsigned a3 = *(const unsigned*)&Ph[(8 + grp) * PS + k0 + 2 * tig + 8];
#pragma unroll
                for (int ntd = 0; ntd < 4; ntd++) {
                    const __half* vb = vthp + (size_t)(ntd * 8 + grp) * Nc + k0 + 2 * tig;
                    unsigned b0 = *(const unsigned*)vb;
                    unsigned b1 = *(const unsigned*)(vb + 8);
                    mma16(xac[ntd][0], xac[ntd][1], xac[ntd][2], xac[ntd][3],
                          a0, a1, a2, a3, b0, b1);
                }
            }
        }

        // cross-warp combine (16 k-slice partials); CBS=34 keeps float2 aligned
#pragma unroll
        for (int ntd = 0; ntd < 4; ntd++) {
            int d = ntd * 8 + 2 * tig;
            *(float2*)&Comb[wid * (16 * CBS) + grp * CBS + d] =
                make_float2(xac[ntd][0], xac[ntd][1]);
            *(float2*)&Comb[wid * (16 * CBS) + (8 + grp) * CBS + d] =
                make_float2(xac[ntd][2], xac[ntd][3]);
        }
        __syncthreads();

        int r = tid >> 5, d = tid & 31;
        float x = 0.f;
#pragma unroll
        for (int w = 0; w < 16; w++)
            x += Comb[w * (16 * CBS) + r * CBS + d];
        g_x[((size_t)(b * Nc + q0 + r)) * Cc + h * 32 + d] = x;
    }
}

// ---------------------------------------------------------------------------
// Kernel 3: output projection + residual via tf32 MMA. Tile 32m x 64n.
// ---------------------------------------------------------------------------
__global__ void __launch_bounds__(256) oproj_mma_kernel(
    const float* __restrict__ Wo, const float* __restrict__ bo,
    const float* __restrict__ query, float* __restrict__ out)
{
    __shared__ float As[32][36];
    __shared__ float Bs[64][36];
    __shared__ float bias_s[64];

    int m0 = blockIdx.x * 32;
    int n0 = blockIdx.y * 64;
    int tid = threadIdx.x;
    int wid = tid >> 5, lane = tid & 31;
    int grp = lane >> 2, tig = lane & 3;
    int mw = wid >> 2, nw = wid & 3;

    if (tid < 64) bias_s[tid] = bo[n0 + tid];

    float acc[2][4];
#pragma unroll
    for (int i = 0; i < 2; i++)
#pragma unroll
        for (int j = 0; j < 4; j++) acc[i][j] = 0.f;

    int arow = tid >> 3, aseg = tid & 7;

    for (int c = 0; c < 8; c++) {
        float4 xa = *(const float4*)(g_x + (size_t)(m0 + arow) * Cc + c * 32 + aseg * 4);
        float4 wb0 = *(const float4*)(Wo + (size_t)(n0 + arow) * Cc + c * 32 + aseg * 4);
        float4 wb1 = *(const float4*)(Wo + (size_t)(n0 + 32 + arow) * Cc + c * 32 + aseg * 4);
        __syncthreads();
        xa.x = to_tf32(xa.x); xa.y = to_tf32(xa.y); xa.z = to_tf32(xa.z); xa.w = to_tf32(xa.w);
        *(float4*)&As[arow][aseg * 4] = xa;
        wb0.x = to_tf32(wb0.x); wb0.y = to_tf32(wb0.y); wb0.z = to_tf32(wb0.z); wb0.w = to_tf32(wb0.w);
        *(float4*)&Bs[arow][aseg * 4] = wb0;
        wb1.x = to_tf32(wb1.x); wb1.y = to_tf32(wb1.y); wb1.z = to_tf32(wb1.z); wb1.w = to_tf32(wb1.w);
        *(float4*)&Bs[32 + arow][aseg * 4] = wb1;
        __syncthreads();

#pragma unroll
        for (int s = 0; s < 4; s++) {
            unsigned a0 = __float_as_uint(As[mw * 16 + grp][s * 8 + tig]);
            unsigned a1 = __float_as_uint(As[mw * 16 + grp + 8][s * 8 + tig]);
            unsigned a2 = __float_as_uint(As[mw * 16 + grp][s * 8 + tig + 4]);
            unsigned a3 = __float_as_uint(As[mw * 16 + grp + 8][s * 8 + tig + 4]);
#pragma unroll
            for (int nt = 0; nt < 2; nt++) {
                unsigned b0 = __float_as_uint(Bs[nw * 16 + nt * 8 + grp][s * 8 + tig]);
                unsigned b1 = __float_as_uint(Bs[nw * 16 + nt * 8 + grp][s * 8 + tig + 4]);
                mma8(acc[nt][0], acc[nt][1], acc[nt][2], acc[nt][3], a0, a1, a2, a3, b0, b1);
            }
        }
    }

#pragma unroll
    for (int nt = 0; nt < 2; nt++) {
        int c0 = n0 + nw * 16 + nt * 8 + 2 * tig;
#pragma unroll
        for (int rr = 0; rr < 2; rr++) {
            int m = m0 + mw * 16 + grp + rr * 8;
            float2 qv = *(const float2*)&query[(size_t)m * Cc + c0];
            float2 ov;
            ov.x = acc[nt][rr * 2 + 0] + bias_s[c0 - n0]     + qv.x;
            ov.y = acc[nt][rr * 2 + 1] + bias_s[c0 - n0 + 1] + qv.y;
            *(float2*)&out[(size_t)m * Cc + c0] = ov;
        }
    }
}

// ---------------------------------------------------------------------------
extern "C" void kernel_launch(void* const* d_in, const int* in_sizes, int n_in,
                              void* d_out, int out_size)
{
    const float* query = (const float*)d_in[0];
    const float* mask  = (const float*)d_in[1];
    const float* Wq = (const float*)d_in[2];
    const float* bq = (const float*)d_in[3];
    const float* Wk = (const float*)d_in[4];
    const float* bk = (const float*)d_in[5];
    const float* Wv = (const float*)d_in[6];
    const float* bv = (const float*)d_in[7];
    const float* Wo = (const float*)d_in[8];
    const float* bo = (const float*)d_in[9];

    float* out_query = (float*)d_out;                       // [B,N,C]
    float* vis       = out_query + (size_t)Bc * Nc * Cc;    // [B,H,N,N]

    dim3 gr(Nc / 256, Nc / 256, Bc);
    rmax_kernel<<<gr, 256>>>(mask);

    dim3 gq((Bc * Nc) / 32, Cc / 64, 3);
    qkv_mma_kernel<<<gq, 256>>>(query, Wq, Wk, Wv, bq, bk, bv);

    // smem: 320 (Q) + 20480 (union) + 16448 (Ph) + 544 (red) floats = 151,168 B
    size_t smem = (size_t)(320 + 20480 + (16 * PS) / 2 + 544) * sizeof(float);
    cudaFuncSetAttribute(attn_kernel, cudaFuncAttributeMaxDynamicSharedMemorySize, (int)smem);
    dim3 ga(Hc, Nc / 16, Bc);   // h fastest -> mask tile shared in L2
    attn_kernel<<<ga, 512, smem>>>(mask, vis);

    dim3 go((Bc * Nc) / 32, Cc / 64);
    oproj_mma_kernel<<<go, 256>>>(Wo, bo, query, out_query);
}

// round 13
// speedup vs baseline: 1.1074x; 1.1074x over previous
#include <cuda_runtime.h>
#include <cuda_fp16.h>
#include <cstdint>

#define Bc 4
#define Nc 2048
#define Cc 256
#define Hc 8
#define DHc 32
#define SCALEF 0.17677669529663687f   // 32^-0.5
#define LGS 2056                      // lg row stride (floats)
#define MSS 260                       // mask stage row stride (floats)
#define KSS 40                        // K/Q stage row stride (halfs)

// ---- scratch (static device allocations) ----
__device__ __half g_qh [Bc*Hc*Nc*DHc];   // Q [bh][n][d], pre-scaled by SCALEF
__device__ __half g_kh [Bc*Hc*Nc*DHc];   // K [bh][n][d]
__device__ __half g_vth[Bc*Hc*DHc*Nc];   // V transposed [bh][d][n]
__device__ float  g_x  [Bc*Nc*Cc];       // attention output [B*N, C]
__device__ unsigned int g_rmaxb[Bc*Nc];  // max_k mask[b,k,q] as monotone uint bits

// ---- MMA helpers ----
__device__ __forceinline__ float to_tf32(float x) {
    unsigned u;
    asm("cvt.rna.tf32.f32 %0, %1;" : "=r"(u) : "f"(x));
    return __uint_as_float(u);
}
__device__ __forceinline__ void mma8(float& d0, float& d1, float& d2, float& d3,
                                     unsigned a0, unsigned a1, unsigned a2, unsigned a3,
                                     unsigned b0, unsigned b1) {
    asm volatile(
        "mma.sync.aligned.m16n8k8.row.col.f32.tf32.tf32.f32 "
        "{%0,%1,%2,%3},{%4,%5,%6,%7},{%8,%9},{%0,%1,%2,%3};"
        : "+f"(d0), "+f"(d1), "+f"(d2), "+f"(d3)
        : "r"(a0), "r"(a1), "r"(a2), "r"(a3), "r"(b0), "r"(b1));
}
__device__ __forceinline__ void mma16(float& d0, float& d1, float& d2, float& d3,
                                      unsigned a0, unsigned a1, unsigned a2, unsigned a3,
                                      unsigned b0, unsigned b1) {
    asm volatile(
        "mma.sync.aligned.m16n8k16.row.col.f32.f16.f16.f32 "
        "{%0,%1,%2,%3},{%4,%5,%6,%7},{%8,%9},{%0,%1,%2,%3};"
        : "+f"(d0), "+f"(d1), "+f"(d2), "+f"(d3)
        : "r"(a0), "r"(a1), "r"(a2), "r"(a3), "r"(b0), "r"(b1));
}
__device__ __forceinline__ unsigned pack_h2(float lo, float hi) {
    __half2 h = __floats2half2_rn(lo, hi);
    return *(unsigned*)&h;
}

// ---------------------------------------------------------------------------
// Kernel 0: column-max of mask via atomicMax on float bits (mask > 0).
// ---------------------------------------------------------------------------
__global__ void __launch_bounds__(256) rmax_kernel(const float* __restrict__ mask)
{
    int q  = blockIdx.x * 256 + threadIdx.x;
    int k0 = blockIdx.y * 256;
    int b  = blockIdx.z;
    const float* mc = mask + (size_t)b * Nc * Nc + q;
    float mx = 0.f;
#pragma unroll 8
    for (int k = 0; k < 256; k++)
        mx = fmaxf(mx, mc[(size_t)(k0 + k) * Nc]);
    atomicMax(&g_rmaxb[b * Nc + q], __float_as_uint(mx));
}

// ---------------------------------------------------------------------------
// Kernel 1: QKV projection via tf32 MMA. Tile 32m x 64n, 8 warps.
// Writes half outputs: Q (pre-scaled), K row-major, V transposed.
// ---------------------------------------------------------------------------
__global__ void __launch_bounds__(256) qkv_mma_kernel(
    const float* __restrict__ X,
    const float* __restrict__ Wq, const float* __restrict__ Wk, const float* __restrict__ Wv,
    const float* __restrict__ bq, const float* __restrict__ bk, const float* __restrict__ bv)
{
    __shared__ float As[32][36];
    __shared__ float Bs[64][36];
    __shared__ float bias_s[64];

    const float* W; const float* bias;
    if (blockIdx.z == 0)      { W = Wq; bias = bq; }
    else if (blockIdx.z == 1) { W = Wk; bias = bk; }
    else                      { W = Wv; bias = bv; }

    int m0 = blockIdx.x * 32;
    int n0 = blockIdx.y * 64;
    int tid = threadIdx.x;
    int wid = tid >> 5, lane = tid & 31;
    int grp = lane >> 2, tig = lane & 3;
    int mw = wid >> 2, nw = wid & 3;

    if (tid < 64) bias_s[tid] = bias[n0 + tid];

    float acc[2][4];
#pragma unroll
    for (int i = 0; i < 2; i++)
#pragma unroll
        for (int j = 0; j < 4; j++) acc[i][j] = 0.f;

    int arow = tid >> 3, aseg = tid & 7;

    for (int c = 0; c < 8; c++) {
        float4 xa = *(const float4*)(X + (size_t)(m0 + arow) * Cc + c * 32 + aseg * 4);
        float4 wb0 = *(const float4*)(W + (size_t)(n0 + arow) * Cc + c * 32 + aseg * 4);
        float4 wb1 = *(const float4*)(W + (size_t)(n0 + 32 + arow) * Cc + c * 32 + aseg * 4);
        __syncthreads();
        xa.x = to_tf32(xa.x); xa.y = to_tf32(xa.y); xa.z = to_tf32(xa.z); xa.w = to_tf32(xa.w);
        *(float4*)&As[arow][aseg * 4] = xa;
        wb0.x = to_tf32(wb0.x); wb0.y = to_tf32(wb0.y); wb0.z = to_tf32(wb0.z); wb0.w = to_tf32(wb0.w);
        *(float4*)&Bs[arow][aseg * 4] = wb0;
        wb1.x = to_tf32(wb1.x); wb1.y = to_tf32(wb1.y); wb1.z = to_tf32(wb1.z); wb1.w = to_tf32(wb1.w);
        *(float4*)&Bs[32 + arow][aseg * 4] = wb1;
        __syncthreads();

#pragma unroll
        for (int s = 0; s < 4; s++) {
            unsigned a0 = __float_as_uint(As[mw * 16 + grp][s * 8 + tig]);
            unsigned a1 = __float_as_uint(As[mw * 16 + grp + 8][s * 8 + tig]);
            unsigned a2 = __float_as_uint(As[mw * 16 + grp][s * 8 + tig + 4]);
            unsigned a3 = __float_as_uint(As[mw * 16 + grp + 8][s * 8 + tig + 4]);
#pragma unroll
            for (int nt = 0; nt < 2; nt++) {
                unsigned b0 = __float_as_uint(Bs[nw * 16 + nt * 8 + grp][s * 8 + tig]);
                unsigned b1 = __float_as_uint(Bs[nw * 16 + nt * 8 + grp][s * 8 + tig + 4]);
                mma8(acc[nt][0], acc[nt][1], acc[nt][2], acc[nt][3], a0, a1, a2, a3, b0, b1);
            }
        }
    }

    // epilogue
#pragma unroll
    for (int nt = 0; nt < 2; nt++) {
        int c0 = n0 + nw * 16 + nt * 8 + 2 * tig;
#pragma unroll
        for (int rr = 0; rr < 2; rr++) {
            int m = m0 + mw * 16 + grp + rr * 8;
            int b = m >> 11, nr = m & (Nc - 1);
            float v0 = acc[nt][rr * 2 + 0] + bias_s[c0 - n0];
            float v1 = acc[nt][rr * 2 + 1] + bias_s[c0 - n0 + 1];
            int h = c0 >> 5, d = c0 & 31;
            size_t bh = (size_t)(b * Hc + h);
            if (blockIdx.z == 0) {
                __half2 hv = __floats2half2_rn(v0 * SCALEF, v1 * SCALEF);
                *(__half2*)&g_qh[(bh * Nc + nr) * DHc + d] = hv;
            } else if (blockIdx.z == 1) {
                __half2 hv = __floats2half2_rn(v0, v1);
                *(__half2*)&g_kh[(bh * Nc + nr) * DHc + d] = hv;
            } else {
                g_vth[(bh * DHc + d) * Nc + nr]     = __float2half_rn(v0);
                g_vth[(bh * DHc + d + 1) * Nc + nr] = __float2half_rn(v1);
            }
        }
    }
}

// ---------------------------------------------------------------------------
// Kernel 2: attention, fp16 mma.sync (m16n8k16). Block = (h, q-tile, b).
// Phase 1: S = Q K^T, K staged as half rows (register prefetch); per-lane
//          running row-max fused into the MMA epilogue (kills the separate
//          max pass over lg).
// Phase 2: softmax fp32 + vis STG.128 + mask (double-buffered);
//          P compacted fp32->half IN PLACE inside lg (skewed per row).
// Phase 3: x = P V via fp16 MMA, V^T fragments LDG'd as half2 from L2.
// ---------------------------------------------------------------------------
__global__ void __launch_bounds__(512) attn_kernel(const float* __restrict__ mask,
                                                   float* __restrict__ vis)
{
    extern __shared__ float sm[];
    float* lg = sm;                       // [16][LGS] fp32 logits -> fp16 P (packed)
    __half* Qsh = (__half*)(sm + 16 * LGS);       // [16][KSS]
    float* St = sm + 16 * LGS + (16 * KSS) / 2;   // stage area (floats view)
    __half* Sth = (__half*)St;                    // half view for K staging
    float* red = sm + 16 * LGS + (16 * KSS) / 2 + 10240;  // [16*17] row-max reduce

    int h  = blockIdx.x;
    int q0 = blockIdx.y * 16;
    int b  = blockIdx.z;
    int bh = b * Hc + h;
    const __half* qhp  = g_qh  + (size_t)bh * Nc * DHc;
    const __half* khp  = g_kh  + (size_t)bh * Nc * DHc;
    const __half* vthp = g_vth + (size_t)bh * DHc * Nc;
    const float* mbase = mask + (size_t)b * Nc * Nc;

    int tid  = threadIdx.x;
    int wid  = tid >> 5;
    int lane = tid & 31;
    int grp  = lane >> 2;                 // 0..7
    int tig  = lane & 3;                  // 0..3

    // stage Q tile (already scaled + half in g_qh)
    if (tid < 256) {
        int q = tid >> 4, dp = tid & 15;
        unsigned v = ((const unsigned*)qhp)[q0 * 16 + tid];
        *(unsigned*)&Qsh[q * KSS + dp * 2] = v;
    }
    __syncthreads();

    // A fragments of Q: 2 k16-steps x 4 regs
    unsigned aq[2][4];
#pragma unroll
    for (int s = 0; s < 2; s++) {
        aq[s][0] = *(const unsigned*)&Qsh[grp * KSS + s * 16 + 2 * tig];
        aq[s][1] = *(const unsigned*)&Qsh[(grp + 8) * KSS + s * 16 + 2 * tig];
        aq[s][2] = *(const unsigned*)&Qsh[grp * KSS + s * 16 + 2 * tig + 8];
        aq[s][3] = *(const unsigned*)&Qsh[(grp + 8) * KSS + s * 16 + 2 * tig + 8];
    }

    // ---- Phase 1: S = Q K^T, 4 chunks of 512 k, register-prefetched;
    //      fused per-lane row-max tracking ----
    float pmx0 = -1e30f, pmx1 = -1e30f;   // running max for rows grp / grp+8
    {
        const uint4* kh4 = (const uint4*)khp;     // 16B = 8 halfs; 4 per k-row
        uint4 pre[4];
#pragma unroll
        for (int j = 0; j < 4; j++) {
            int idx = tid + j * 512;
            pre[j] = kh4[idx];                    // row=idx>>2, seg=idx&3
        }

        for (int c = 0; c < 4; c++) {
#pragma unroll
            for (int j = 0; j < 4; j++) {
                int idx = tid + j * 512;
                int row = idx >> 2, seg = idx & 3;
                *(uint4*)&Sth[row * KSS + seg * 8] = pre[j];
            }
            if (c < 3) {
#pragma unroll
                for (int j = 0; j < 4; j++) {
                    int idx = tid + j * 512;
                    pre[j] = kh4[(c + 1) * 2048 + idx];
                }
            }
            __syncthreads();

#pragma unroll
            for (int nt = 0; nt < 4; nt++) {
                int kb = wid * 32 + nt * 8;
                float d0 = 0.f, d1 = 0.f, d2 = 0.f, d3 = 0.f;
#pragma unroll
                for (int s = 0; s < 2; s++) {
                    unsigned b0 = *(const unsigned*)&Sth[(kb + grp) * KSS + s * 16 + 2 * tig];
                    unsigned b1 = *(const unsigned*)&Sth[(kb + grp) * KSS + s * 16 + 2 * tig + 8];
                    mma16(d0, d1, d2, d3, aq[s][0], aq[s][1], aq[s][2], aq[s][3], b0, b1);
                }
                pmx0 = fmaxf(pmx0, fmaxf(d0, d1));
                pmx1 = fmaxf(pmx1, fmaxf(d2, d3));
                int kg = c * 512 + kb + 2 * tig;
                *(float2*)&lg[grp * LGS + kg]       = make_float2(d0, d1);
                *(float2*)&lg[(grp + 8) * LGS + kg] = make_float2(d2, d3);
            }
            __syncthreads();
        }
    }

    // reduce lane maxima: over tig (quad), then cross-warp via red[row][warp]
    pmx0 = fmaxf(pmx0, __shfl_xor_sync(0xffffffffu, pmx0, 1));
    pmx0 = fmaxf(pmx0, __shfl_xor_sync(0xffffffffu, pmx0, 2));
    pmx1 = fmaxf(pmx1, __shfl_xor_sync(0xffffffffu, pmx1, 1));
    pmx1 = fmaxf(pmx1, __shfl_xor_sync(0xffffffffu, pmx1, 2));
    if (tig == 0) {
        red[grp * 17 + wid]       = pmx0;
        red[(8 + grp) * 17 + wid] = pmx1;
    }
    __syncthreads();

    // ---- Phase 2: softmax (warp = row) + vis + mask; P -> half in place ----
    {
        float* row = lg + wid * LGS;
        __half* hrow = (__half*)((char*)(lg) + (size_t)wid * LGS * 4 + (wid & 7) * 16);

        float mx = -1e30f;
#pragma unroll
        for (int w = 0; w < 16; w++)
            mx = fmaxf(mx, red[wid * 17 + w]);    // broadcast LDS, 16 scalars

        float s = 0.f;
#pragma unroll
        for (int i = 0; i < 16; i++) {
            float4 r = *(float4*)&row[i * 128 + lane * 4];
            r.x = __expf(r.x - mx); r.y = __expf(r.y - mx);
            r.z = __expf(r.z - mx); r.w = __expf(r.w - mx);
            *(float4*)&row[i * 128 + lane * 4] = r;
            s += r.x + r.y + r.z + r.w;
        }
#pragma unroll
        for (int o = 16; o; o >>= 1) s += __shfl_xor_sync(0xffffffffu, s, o);
        float inv = 1.f / s;
        float rmx = 1.f / __uint_as_float(g_rmaxb[b * Nc + q0 + wid]);

        float* visrow = vis + ((size_t)bh * Nc + q0 + wid) * Nc;

        int skk = tid >> 1;                 // 0..255
        int sc8 = (tid & 1) * 8;            // 0 or 8
        const float* mp0 = mbase + (size_t)skk * Nc + q0 + sc8;
        float4 a0 = ((const float4*)mp0)[0];
        float4 a1 = ((const float4*)mp0)[1];

        for (int ch = 0; ch < 8; ch++) {
            float* Sb = St + (ch & 1) * 4160;           // [16 q][MSS]
            Sb[(sc8 + 0) * MSS + skk] = a0.x;
            Sb[(sc8 + 1) * MSS + skk] = a0.y;
            Sb[(sc8 + 2) * MSS + skk] = a0.z;
            Sb[(sc8 + 3) * MSS + skk] = a0.w;
            Sb[(sc8 + 4) * MSS + skk] = a1.x;
            Sb[(sc8 + 5) * MSS + skk] = a1.y;
            Sb[(sc8 + 6) * MSS + skk] = a1.z;
            Sb[(sc8 + 7) * MSS + skk] = a1.w;
            if (ch < 7) {
                const float* mn = mbase + (size_t)((ch + 1) * 256 + skk) * Nc + q0 + sc8;
                a0 = ((const float4*)mn)[0];
                a1 = ((const float4*)mn)[1];
            }
            __syncthreads();

#pragma unroll
            for (int i = 0; i < 2; i++) {
                int kk = i * 128 + lane * 4;
                int k  = ch * 256 + kk;
                float4 e = *(const float4*)&row[k];
                float4 p = make_float4(e.x * inv, e.y * inv, e.z * inv, e.w * inv);
                *(float4*)&visrow[k] = p;                      // pre-mask prob
                float4 m4 = *(const float4*)&Sb[wid * MSS + kk];
                unsigned h0 = pack_h2(p.x * m4.x * rmx, p.y * m4.y * rmx);
                unsigned h1 = pack_h2(p.z * m4.z * rmx, p.w * m4.w * rmx);
                uint2 w = make_uint2(h0, h1);
                *(uint2*)&hrow[k] = w;                         // in-place half P
            }
        }
    }
    __syncthreads();

    // ---- Phase 3: x = P V via fp16 MMA. warp = (d-tile, k-quarter) ----
    {
        int dt = (wid & 3) * 8;             // d-tile base
        int kq = wid >> 2;                  // k quarter (512 k each)
        float x0 = 0.f, x1 = 0.f, x2 = 0.f, x3 = 0.f;

        const __half* hg0 = (const __half*)((char*)(lg) + (size_t)grp * LGS * 4 + (grp & 7) * 16);
        const __half* hg1 = (const __half*)((char*)(lg) + (size_t)(grp + 8) * LGS * 4 + (grp & 7) * 16);

#pragma unroll 4
        for (int s2 = 0; s2 < 32; s2++) {
            int k0 = kq * 512 + s2 * 16;
            unsigned a0 = *(const unsigned*)&hg0[k0 + 2 * tig];
            unsigned a1 = *(const unsigned*)&hg1[k0 + 2 * tig];
            unsigned a2 = *(const unsigned*)&hg0[k0 + 2 * tig + 8];
            unsigned a3 = *(const unsigned*)&hg1[k0 + 2 * tig + 8];
            unsigned b0 = *(const unsigned*)&vthp[(size_t)(dt + grp) * Nc + k0 + 2 * tig];
            unsigned b1 = *(const unsigned*)&vthp[(size_t)(dt + grp) * Nc + k0 + 2 * tig + 8];
            mma16(x0, x1, x2, x3, a0, a1, a2, a3, b0, b1);
        }

        // cross-warp combine over the 4 k-quarters
        St[(kq * 16 + grp) * 33 + dt + 2 * tig]     = x0;
        St[(kq * 16 + grp) * 33 + dt + 2 * tig + 1] = x1;
        St[(kq * 16 + grp + 8) * 33 + dt + 2 * tig]     = x2;
        St[(kq * 16 + grp + 8) * 33 + dt + 2 * tig + 1] = x3;
        __syncthreads();

        int q = tid >> 5, d = tid & 31;
        float x = St[q * 33 + d] + St[(16 + q) * 33 + d]
                + St[(32 + q) * 33 + d] + St[(48 + q) * 33 + d];
        g_x[((size_t)(b * Nc + q0 + q)) * Cc + h * 32 + d] = x;
    }
}

// ---------------------------------------------------------------------------
// Kernel 3: output projection + residual via tf32 MMA. Tile 32m x 64n.
// ---------------------------------------------------------------------------
__global__ void __launch_bounds__(256) oproj_mma_kernel(
    const float* __restrict__ Wo, const float* __restrict__ bo,
    const float* __restrict__ query, float* __restrict__ out)
{
    __shared__ float As[32][36];
    __shared__ float Bs[64][36];
    __shared__ float bias_s[64];

    int m0 = blockIdx.x * 32;
    int n0 = blockIdx.y * 64;
    int tid = threadIdx.x;
    int wid = tid >> 5, lane = tid & 31;
    int grp = lane >> 2, tig = lane & 3;
    int mw = wid >> 2, nw = wid & 3;

    if (tid < 64) bias_s[tid] = bo[n0 + tid];

    float acc[2][4];
#pragma unroll
    for (int i = 0; i < 2; i++)
#pragma unroll
        for (int j = 0; j < 4; j++) acc[i][j] = 0.f;

    int arow = tid >> 3, aseg = tid & 7;

    for (int c = 0; c < 8; c++) {
        float4 xa = *(const float4*)(g_x + (size_t)(m0 + arow) * Cc + c * 32 + aseg * 4);
        float4 wb0 = *(const float4*)(Wo + (size_t)(n0 + arow) * Cc + c * 32 + aseg * 4);
        float4 wb1 = *(const float4*)(Wo + (size_t)(n0 + 32 + arow) * Cc + c * 32 + aseg * 4);
        __syncthreads();
        xa.x = to_tf32(xa.x); xa.y = to_tf32(xa.y); xa.z = to_tf32(xa.z); xa.w = to_tf32(xa.w);
        *(float4*)&As[arow][aseg * 4] = xa;
        wb0.x = to_tf32(wb0.x); wb0.y = to_tf32(wb0.y); wb0.z = to_tf32(wb0.z); wb0.w = to_tf32(wb0.w);
        *(float4*)&Bs[arow][aseg * 4] = wb0;
        wb1.x = to_tf32(wb1.x); wb1.y = to_tf32(wb1.y); wb1.z = to_tf32(wb1.z); wb1.w = to_tf32(wb1.w);
        *(float4*)&Bs[32 + arow][aseg * 4] = wb1;
        __syncthreads();

#pragma unroll
        for (int s = 0; s < 4; s++) {
            unsigned a0 = __float_as_uint(As[mw * 16 + grp][s * 8 + tig]);
            unsigned a1 = __float_as_uint(As[mw * 16 + grp + 8][s * 8 + tig]);
            unsigned a2 = __float_as_uint(As[mw * 16 + grp][s * 8 + tig + 4]);
            unsigned a3 = __float_as_uint(As[mw * 16 + grp + 8][s * 8 + tig + 4]);
#pragma unroll
            for (int nt = 0; nt < 2; nt++) {
                unsigned b0 = __float_as_uint(Bs[nw * 16 + nt * 8 + grp][s * 8 + tig]);
                unsigned b1 = __float_as_uint(Bs[nw * 16 + nt * 8 + grp][s * 8 + tig + 4]);
                mma8(acc[nt][0], acc[nt][1], acc[nt][2], acc[nt][3], a0, a1, a2, a3, b0, b1);
            }
        }
    }

#pragma unroll
    for (int nt = 0; nt < 2; nt++) {
        int c0 = n0 + nw * 16 + nt * 8 + 2 * tig;
#pragma unroll
        for (int rr = 0; rr < 2; rr++) {
            int m = m0 + mw * 16 + grp + rr * 8;
            float2 qv = *(const float2*)&query[(size_t)m * Cc + c0];
            float2 ov;
            ov.x = acc[nt][rr * 2 + 0] + bias_s[c0 - n0]     + qv.x;
            ov.y = acc[nt][rr * 2 + 1] + bias_s[c0 - n0 + 1] + qv.y;
            *(float2*)&out[(size_t)m * Cc + c0] = ov;
        }
    }
}

// ---------------------------------------------------------------------------
extern "C" void kernel_launch(void* const* d_in, const int* in_sizes, int n_in,
                              void* d_out, int out_size)
{
    const float* query = (const float*)d_in[0];
    const float* mask  = (const float*)d_in[1];
    const float* Wq = (const float*)d_in[2];
    const float* bq = (const float*)d_in[3];
    const float* Wk = (const float*)d_in[4];
    const float* bk = (const float*)d_in[5];
    const float* Wv = (const float*)d_in[6];
    const float* bv = (const float*)d_in[7];
    const float* Wo = (const float*)d_in[8];
    const float* bo = (const float*)d_in[9];

    float* out_query = (float*)d_out;                       // [B,N,C]
    float* vis       = out_query + (size_t)Bc * Nc * Cc;    // [B,H,N,N]

    dim3 gr(Nc / 256, Nc / 256, Bc);
    rmax_kernel<<<gr, 256>>>(mask);

    dim3 gq((Bc * Nc) / 32, Cc / 64, 3);
    qkv_mma_kernel<<<gq, 256>>>(query, Wq, Wk, Wv, bq, bk, bv);

    // smem: lg 131584 + Qsh 1280 + stage 40960 + red 1088 = 174,912 B
    size_t smem = (size_t)(16 * LGS * 4 + 16 * KSS * 2 + 40960 + 272 * 4);
    cudaFuncSetAttribute(attn_kernel, cudaFuncAttributeMaxDynamicSharedMemorySize, (int)smem);
    dim3 ga(Hc, Nc / 16, Bc);   // h fastest -> mask tile shared in L2
    attn_kernel<<<ga, 512, smem>>>(mask, vis);

    dim3 go((Bc * Nc) / 32, Cc / 64);
    oproj_mma_kernel<<<go, 256>>>(Wo, bo, query, out_query);
}

// round 15
// speedup vs baseline: 1.2248x; 1.1060x over previous
#include <cuda_runtime.h>
#include <cuda_fp16.h>
#include <cstdint>

#define Bc 4
#define Nc 2048
#define Cc 256
#define Hc 8
#define DHc 32
#define SCALEF 0.17677669529663687f   // 32^-0.5
#define LGS 2056                      // lg row stride (floats)
#define KSS 40                        // K/Q stage row stride (halfs)

// ---- scratch (static device allocations) ----
__device__ __half g_qh [Bc*Hc*Nc*DHc];   // Q [bh][n][d], pre-scaled by SCALEF
__device__ __half g_kh [Bc*Hc*Nc*DHc];   // K [bh][n][d]
__device__ __half g_vth[Bc*Hc*DHc*Nc];   // V transposed [bh][d][n]
__device__ __half g_mt [(size_t)Bc*Nc*Nc]; // normalized mask, TRANSPOSED [b][q][k]
__device__ float  g_x  [Bc*Nc*Cc];       // attention output [B*N, C]
__device__ unsigned int g_rmaxb[Bc*Nc];  // max_k mask[b,k,q] as monotone uint bits

// ---- MMA helpers ----
__device__ __forceinline__ float to_tf32(float x) {
    unsigned u;
    asm("cvt.rna.tf32.f32 %0, %1;" : "=r"(u) : "f"(x));
    return __uint_as_float(u);
}
__device__ __forceinline__ void mma8(float& d0, float& d1, float& d2, float& d3,
                                     unsigned a0, unsigned a1, unsigned a2, unsigned a3,
                                     unsigned b0, unsigned b1) {
    asm volatile(
        "mma.sync.aligned.m16n8k8.row.col.f32.tf32.tf32.f32 "
        "{%0,%1,%2,%3},{%4,%5,%6,%7},{%8,%9},{%0,%1,%2,%3};"
        : "+f"(d0), "+f"(d1), "+f"(d2), "+f"(d3)
        : "r"(a0), "r"(a1), "r"(a2), "r"(a3), "r"(b0), "r"(b1));
}
__device__ __forceinline__ void mma16(float& d0, float& d1, float& d2, float& d3,
                                      unsigned a0, unsigned a1, unsigned a2, unsigned a3,
                                      unsigned b0, unsigned b1) {
    asm volatile(
        "mma.sync.aligned.m16n8k16.row.col.f32.f16.f16.f32 "
        "{%0,%1,%2,%3},{%4,%5,%6,%7},{%8,%9},{%0,%1,%2,%3};"
        : "+f"(d0), "+f"(d1), "+f"(d2), "+f"(d3)
        : "r"(a0), "r"(a1), "r"(a2), "r"(a3), "r"(b0), "r"(b1));
}
__device__ __forceinline__ unsigned pack_h2(float lo, float hi) {
    __half2 h = __floats2half2_rn(lo, hi);
    return *(unsigned*)&h;
}

// ---------------------------------------------------------------------------
// Kernel 0: column-max of mask via atomicMax on float bits (mask > 0).
// ---------------------------------------------------------------------------
__global__ void __launch_bounds__(256) rmax_kernel(const float* __restrict__ mask)
{
    int q  = blockIdx.x * 256 + threadIdx.x;
    int k0 = blockIdx.y * 256;
    int b  = blockIdx.z;
    const float* mc = mask + (size_t)b * Nc * Nc + q;
    float mx = 0.f;
#pragma unroll 8
    for (int k = 0; k < 256; k++)
        mx = fmaxf(mx, mc[(size_t)(k0 + k) * Nc]);
    atomicMax(&g_rmaxb[b * Nc + q], __float_as_uint(mx));
}

// ---------------------------------------------------------------------------
// Kernel 0b: transpose + normalize mask into half: g_mt[b][q][k] =
//            half(mask[b][k][q] / colmax[b][q]).  64x64 tiles via smem.
// ---------------------------------------------------------------------------
__global__ void __launch_bounds__(256) maskt_kernel(const float* __restrict__ mask)
{
    __shared__ float t[64][65];
    int q0 = blockIdx.x * 64;
    int k0 = blockIdx.y * 64;
    int b  = blockIdx.z;
    int tid = threadIdx.x;

#pragma unroll
    for (int j = 0; j < 4; j++) {
        int idx = tid + j * 256;
        int kr = idx >> 4;
        int qc = (idx & 15) * 4;
        float4 v = *(const float4*)&mask[((size_t)b * Nc + k0 + kr) * Nc + q0 + qc];
        t[qc + 0][kr] = v.x; t[qc + 1][kr] = v.y;
        t[qc + 2][kr] = v.z; t[qc + 3][kr] = v.w;
    }
    __syncthreads();

    int qr = tid >> 2;
    int ks = (tid & 3) * 16;
    float rv = 1.f / __uint_as_float(g_rmaxb[b * Nc + q0 + qr]);
    __align__(16) __half hbuf[16];
#pragma unroll
    for (int i = 0; i < 16; i++)
        hbuf[i] = __float2half_rn(t[qr][ks + i] * rv);
    __half* dst = g_mt + ((size_t)b * Nc + q0 + qr) * Nc + k0 + ks;
    *(uint4*)dst       = *(uint4*)hbuf;
    *(uint4*)(dst + 8) = *(uint4*)(hbuf + 8);
}

// ---------------------------------------------------------------------------
// Kernel 1: QKV projection via tf32 MMA. Tile 32m x 64n, 8 warps.
// Writes half outputs: Q (pre-scaled), K row-major, V transposed.
// ---------------------------------------------------------------------------
__global__ void __launch_bounds__(256) qkv_mma_kernel(
    const float* __restrict__ X,
    const float* __restrict__ Wq, const float* __restrict__ Wk, const float* __restrict__ Wv,
    const float* __restrict__ bq, const float* __restrict__ bk, const float* __restrict__ bv)
{
    __shared__ float As[32][36];
    __shared__ float Bs[64][36];
    __shared__ float bias_s[64];

    const float* W; const float* bias;
    if (blockIdx.z == 0)      { W = Wq; bias = bq; }
    else if (blockIdx.z == 1) { W = Wk; bias = bk; }
    else                      { W = Wv; bias = bv; }

    int m0 = blockIdx.x * 32;
    int n0 = blockIdx.y * 64;
    int tid = threadIdx.x;
    int wid = tid >> 5, lane = tid & 31;
    int grp = lane >> 2, tig = lane & 3;
    int mw = wid >> 2, nw = wid & 3;

    if (tid < 64) bias_s[tid] = bias[n0 + tid];

    float acc[2][4];
#pragma unroll
    for (int i = 0; i < 2; i++)
#pragma unroll
        for (int j = 0; j < 4; j++) acc[i][j] = 0.f;

    int arow = tid >> 3, aseg = tid & 7;

    for (int c = 0; c < 8; c++) {
        float4 xa = *(const float4*)(X + (size_t)(m0 + arow) * Cc + c * 32 + aseg * 4);
        float4 wb0 = *(const float4*)(W + (size_t)(n0 + arow) * Cc + c * 32 + aseg * 4);
        float4 wb1 = *(const float4*)(W + (size_t)(n0 + 32 + arow) * Cc + c * 32 + aseg * 4);
        __syncthreads();
        xa.x = to_tf32(xa.x); xa.y = to_tf32(xa.y); xa.z = to_tf32(xa.z); xa.w = to_tf32(xa.w);
        *(float4*)&As[arow][aseg * 4] = xa;
        wb0.x = to_tf32(wb0.x); wb0.y = to_tf32(wb0.y); wb0.z = to_tf32(wb0.z); wb0.w = to_tf32(wb0.w);
        *(float4*)&Bs[arow][aseg * 4] = wb0;
        wb1.x = to_tf32(wb1.x); wb1.y = to_tf32(wb1.y); wb1.z = to_tf32(wb1.z); wb1.w = to_tf32(wb1.w);
        *(float4*)&Bs[32 + arow][aseg * 4] = wb1;
        __syncthreads();

#pragma unroll
        for (int s = 0; s < 4; s++) {
            unsigned a0 = __float_as_uint(As[mw * 16 + grp][s * 8 + tig]);
            unsigned a1 = __float_as_uint(As[mw * 16 + grp + 8][s * 8 + tig]);
            unsigned a2 = __float_as_uint(As[mw * 16 + grp][s * 8 + tig + 4]);
            unsigned a3 = __float_as_uint(As[mw * 16 + grp + 8][s * 8 + tig + 4]);
#pragma unroll
            for (int nt = 0; nt < 2; nt++) {
                unsigned b0 = __float_as_uint(Bs[nw * 16 + nt * 8 + grp][s * 8 + tig]);
                unsigned b1 = __float_as_uint(Bs[nw * 16 + nt * 8 + grp][s * 8 + tig + 4]);
                mma8(acc[nt][0], acc[nt][1], acc[nt][2], acc[nt][3], a0, a1, a2, a3, b0, b1);
            }
        }
    }

    // epilogue
#pragma unroll
    for (int nt = 0; nt < 2; nt++) {
        int c0 = n0 + nw * 16 + nt * 8 + 2 * tig;
#pragma unroll
        for (int rr = 0; rr < 2; rr++) {
            int m = m0 + mw * 16 + grp + rr * 8;
            int b = m >> 11, nr = m & (Nc - 1);
            float v0 = acc[nt][rr * 2 + 0] + bias_s[c0 - n0];
            float v1 = acc[nt][rr * 2 + 1] + bias_s[c0 - n0 + 1];
            int h = c0 >> 5, d = c0 & 31;
            size_t bh = (size_t)(b * Hc + h);
            if (blockIdx.z == 0) {
                __half2 hv = __floats2half2_rn(v0 * SCALEF, v1 * SCALEF);
                *(__half2*)&g_qh[(bh * Nc + nr) * DHc + d] = hv;
            } else if (blockIdx.z == 1) {
                __half2 hv = __floats2half2_rn(v0, v1);
                *(__half2*)&g_kh[(bh * Nc + nr) * DHc + d] = hv;
            } else {
                g_vth[(bh * DHc + d) * Nc + nr]     = __float2half_rn(v0);
                g_vth[(bh * DHc + d + 1) * Nc + nr] = __float2half_rn(v1);
            }
        }
    }
}

// ---------------------------------------------------------------------------
// Kernel 2: attention, fp16 mma.sync (m16n8k16). Block = (h, q-tile, b).
// Phase 1: S = Q K^T, K staged as half rows (register prefetch); fused
//          per-lane row-max tracking.
// Phase 2: softmax fp32 + vis STG.128 + normalized-mask multiply from g_mt
//          (coalesced half2 reads, NO staging, NO barriers);
//          P compacted fp32->half IN PLACE inside lg (skewed per row).
// Phase 3: x = P V via fp16 MMA, V^T fragments LDG'd as half2 from L2.
// ---------------------------------------------------------------------------
__global__ void __launch_bounds__(512) attn_kernel(const float* __restrict__ mask,
                                                   float* __restrict__ vis)
{
    extern __shared__ float sm[];
    float* lg = sm;                       // [16][LGS] fp32 logits -> fp16 P (packed)
    __half* Qsh = (__half*)(sm + 16 * LGS);       // [16][KSS]
    float* St = sm + 16 * LGS + (16 * KSS) / 2;   // stage area (floats view)
    __half* Sth = (__half*)St;                    // half view for K staging
    float* red = sm + 16 * LGS + (16 * KSS) / 2 + 10240;  // [16*17] row-max reduce

    int h  = blockIdx.x;
    int q0 = blockIdx.y * 16;
    int b  = blockIdx.z;
    int bh = b * Hc + h;
    const __half* qhp  = g_qh  + (size_t)bh * Nc * DHc;
    const __half* khp  = g_kh  + (size_t)bh * Nc * DHc;
    const __half* vthp = g_vth + (size_t)bh * DHc * Nc;

    int tid  = threadIdx.x;
    int wid  = tid >> 5;
    int lane = tid & 31;
    int grp  = lane >> 2;                 // 0..7
    int tig  = lane & 3;                  // 0..3

    // stage Q tile (already scaled + half in g_qh)
    if (tid < 256) {
        int q = tid >> 4, dp = tid & 15;
        unsigned v = ((const unsigned*)qhp)[q0 * 16 + tid];
        *(unsigned*)&Qsh[q * KSS + dp * 2] = v;
    }
    __syncthreads();

    // A fragments of Q: 2 k16-steps x 4 regs
    unsigned aq[2][4];
#pragma unroll
    for (int s = 0; s < 2; s++) {
        aq[s][0] = *(const unsigned*)&Qsh[grp * KSS + s * 16 + 2 * tig];
        aq[s][1] = *(const unsigned*)&Qsh[(grp + 8) * KSS + s * 16 + 2 * tig];
        aq[s][2] = *(const unsigned*)&Qsh[grp * KSS + s * 16 + 2 * tig + 8];
        aq[s][3] = *(const unsigned*)&Qsh[(grp + 8) * KSS + s * 16 + 2 * tig + 8];
    }

    // ---- Phase 1: S = Q K^T, 4 chunks of 512 k, register-prefetched;
    //      fused per-lane row-max tracking ----
    float pmx0 = -1e30f, pmx1 = -1e30f;   // running max for rows grp / grp+8
    {
        const uint4* kh4 = (const uint4*)khp;     // 16B = 8 halfs; 4 per k-row
        uint4 pre[4];
#pragma unroll
        for (int j = 0; j < 4; j++) {
            int idx = tid + j * 512;
            pre[j] = kh4[idx];                    // row=idx>>2, seg=idx&3
        }

        for (int c = 0; c < 4; c++) {
#pragma unroll
            for (int j = 0; j < 4; j++) {
                int idx = tid + j * 512;
                int row = idx >> 2, seg = idx & 3;
                *(uint4*)&Sth[row * KSS + seg * 8] = pre[j];
            }
            if (c < 3) {
#pragma unroll
                for (int j = 0; j < 4; j++) {
                    int idx = tid + j * 512;
                    pre[j] = kh4[(c + 1) * 2048 + idx];
                }
            }
            __syncthreads();

#pragma unroll
            for (int nt = 0; nt < 4; nt++) {
                int kb = wid * 32 + nt * 8;
                float d0 = 0.f, d1 = 0.f, d2 = 0.f, d3 = 0.f;
#pragma unroll
                for (int s = 0; s < 2; s++) {
                    unsigned b0 = *(const unsigned*)&Sth[(kb + grp) * KSS + s * 16 + 2 * tig];
                    unsigned b1 = *(const unsigned*)&Sth[(kb + grp) * KSS + s * 16 + 2 * tig + 8];
                    mma16(d0, d1, d2, d3, aq[s][0], aq[s][1], aq[s][2], aq[s][3], b0, b1);
                }
                pmx0 = fmaxf(pmx0, fmaxf(d0, d1));
                pmx1 = fmaxf(pmx1, fmaxf(d2, d3));
                int kg = c * 512 + kb + 2 * tig;
                *(float2*)&lg[grp * LGS + kg]       = make_float2(d0, d1);
                *(float2*)&lg[(grp + 8) * LGS + kg] = make_float2(d2, d3);
            }
            __syncthreads();
        }
    }

    // reduce lane maxima: over tig (quad), then cross-warp via red[row][warp]
    pmx0 = fmaxf(pmx0, __shfl_xor_sync(0xffffffffu, pmx0, 1));
    pmx0 = fmaxf(pmx0, __shfl_xor_sync(0xffffffffu, pmx0, 2));
    pmx1 = fmaxf(pmx1, __shfl_xor_sync(0xffffffffu, pmx1, 1));
    pmx1 = fmaxf(pmx1, __shfl_xor_sync(0xffffffffu, pmx1, 2));
    if (tig == 0) {
        red[grp * 17 + wid]       = pmx0;
        red[(8 + grp) * 17 + wid] = pmx1;
    }
    __syncthreads();

    // ---- Phase 2: softmax (warp = row) + vis + mt multiply; barrier-free ----
    {
        float* row = lg + wid * LGS;
        __half* hrow = (__half*)((char*)(lg) + (size_t)wid * LGS * 4 + (wid & 7) * 16);

        float mx = -1e30f;
#pragma unroll
        for (int w = 0; w < 16; w++)
            mx = fmaxf(mx, red[wid * 17 + w]);    // broadcast LDS, 16 scalars

        float s = 0.f;
#pragma unroll
        for (int i = 0; i < 16; i++) {
            float4 r = *(float4*)&row[i * 128 + lane * 4];
            r.x = __expf(r.x - mx); r.y = __expf(r.y - mx);
            r.z = __expf(r.z - mx); r.w = __expf(r.w - mx);
            *(float4*)&row[i * 128 + lane * 4] = r;
            s += r.x + r.y + r.z + r.w;
        }
#pragma unroll
        for (int o = 16; o; o >>= 1) s += __shfl_xor_sync(0xffffffffu, s, o);
        float inv = 1.f / s;

        float* visrow = vis + ((size_t)bh * Nc + q0 + wid) * Nc;
        const __half* mtrow = g_mt + ((size_t)b * Nc + q0 + wid) * Nc;

#pragma unroll
        for (int i = 0; i < 16; i++) {
            int k = i * 128 + lane * 4;
            float4 e = *(const float4*)&row[k];
            float4 p = make_float4(e.x * inv, e.y * inv, e.z * inv, e.w * inv);
            *(float4*)&visrow[k] = p;                          // pre-mask prob
            uint2 mraw = *(const uint2*)&mtrow[k];             // 4 normalized halfs
            float2 ma = __half22float2(*(__half2*)&mraw.x);
            float2 mb = __half22float2(*(__half2*)&mraw.y);
            unsigned h0 = pack_h2(p.x * ma.x, p.y * ma.y);
            unsigned h1 = pack_h2(p.z * mb.x, p.w * mb.y);
            uint2 w = make_uint2(h0, h1);
            *(uint2*)&hrow[k] = w;                             // in-place half P
        }
    }
    __syncthreads();

    // ---- Phase 3: x = P V via fp16 MMA. warp = (d-tile, k-quarter) ----
    {
        int dt = (wid & 3) * 8;             // d-tile base
        int kq = wid >> 2;                  // k quarter (512 k each)
        float x0 = 0.f, x1 = 0.f, x2 = 0.f, x3 = 0.f;

        const __half* hg0 = (const __half*)((char*)(lg) + (size_t)grp * LGS * 4 + (grp & 7) * 16);
        const __half* hg1 = (const __half*)((char*)(lg) + (size_t)(grp + 8) * LGS * 4 + (grp & 7) * 16);

#pragma unroll 4
        for (int s2 = 0; s2 < 32; s2++) {
            int k0 = kq * 512 + s2 * 16;
            unsigned a0 = *(const unsigned*)&hg0[k0 + 2 * tig];
            unsigned a1 = *(const unsigned*)&hg1[k0 + 2 * tig];
            unsigned a2 = *(const unsigned*)&hg0[k0 + 2 * tig + 8];
            unsigned a3 = *(const unsigned*)&hg1[k0 + 2 * tig + 8];
            unsigned b0 = *(const unsigned*)&vthp[(size_t)(dt + grp) * Nc + k0 + 2 * tig];
            unsigned b1 = *(const unsigned*)&vthp[(size_t)(dt + grp) * Nc + k0 + 2 * tig + 8];
            mma16(x0, x1, x2, x3, a0, a1, a2, a3, b0, b1);
        }

        // cross-warp combine over the 4 k-quarters
        St[(kq * 16 + grp) * 33 + dt + 2 * tig]     = x0;
        St[(kq * 16 + grp) * 33 + dt + 2 * tig + 1] = x1;
        St[(kq * 16 + grp + 8) * 33 + dt + 2 * tig]     = x2;
        St[(kq * 16 + grp + 8) * 33 + dt + 2 * tig + 1] = x3;
        __syncthreads();

        int q = tid >> 5, d = tid & 31;
        float x = St[q * 33 + d] + St[(16 + q) * 33 + d]
                + St[(32 + q) * 33 + d] + St[(48 + q) * 33 + d];
        g_x[((size_t)(b * Nc + q0 + q)) * Cc + h * 32 + d] = x;
    }
}

// ---------------------------------------------------------------------------
// Kernel 3: output projection + residual via tf32 MMA. Tile 32m x 64n.
// ---------------------------------------------------------------------------
__global__ void __launch_bounds__(256) oproj_mma_kernel(
    const float* __restrict__ Wo, const float* __restrict__ bo,
    const float* __restrict__ query, float* __restrict__ out)
{
    __shared__ float As[32][36];
    __shared__ float Bs[64][36];
    __shared__ float bias_s[64];

    int m0 = blockIdx.x * 32;
    int n0 = blockIdx.y * 64;
    int tid = threadIdx.x;
    int wid = tid >> 5, lane = tid & 31;
    int grp = lane >> 2, tig = lane & 3;
    int mw = wid >> 2, nw = wid & 3;

    if (tid < 64) bias_s[tid] = bo[n0 + tid];

    float acc[2][4];
#pragma unroll
    for (int i = 0; i < 2; i++)
#pragma unroll
        for (int j = 0; j < 4; j++) acc[i][j] = 0.f;

    int arow = tid >> 3, aseg = tid & 7;

    for (int c = 0; c < 8; c++) {
        float4 xa = *(const float4*)(g_x + (size_t)(m0 + arow) * Cc + c * 32 + aseg * 4);
        float4 wb0 = *(const float4*)(Wo + (size_t)(n0 + arow) * Cc + c * 32 + aseg * 4);
        float4 wb1 = *(const float4*)(Wo + (size_t)(n0 + 32 + arow) * Cc + c * 32 + aseg * 4);
        __syncthreads();
        xa.x = to_tf32(xa.x); xa.y = to_tf32(xa.y); xa.z = to_tf32(xa.z); xa.w = to_tf32(xa.w);
        *(float4*)&As[arow][aseg * 4] = xa;
        wb0.x = to_tf32(wb0.x); wb0.y = to_tf32(wb0.y); wb0.z = to_tf32(wb0.z); wb0.w = to_tf32(wb0.w);
        *(float4*)&Bs[arow][aseg * 4] = wb0;
        wb1.x = to_tf32(wb1.x); wb1.y = to_tf32(wb1.y); wb1.z = to_tf32(wb1.z); wb1.w = to_tf32(wb1.w);
        *(float4*)&Bs[32 + arow][aseg * 4] = wb1;
        __syncthreads();

#pragma unroll
        for (int s = 0; s < 4; s++) {
            unsigned a0 = __float_as_uint(As[mw * 16 + grp][s * 8 + tig]);
            unsigned a1 = __float_as_uint(As[mw * 16 + grp + 8][s * 8 + tig]);
            unsigned a2 = __float_as_uint(As[mw * 16 + grp][s * 8 + tig + 4]);
            unsigned a3 = __float_as_uint(As[mw * 16 + grp + 8][s * 8 + tig + 4]);
#pragma unroll
            for (int nt = 0; nt < 2; nt++) {
                unsigned b0 = __float_as_uint(Bs[nw * 16 + nt * 8 + grp][s * 8 + tig]);
                unsigned b1 = __float_as_uint(Bs[nw * 16 + nt * 8 + grp][s * 8 + tig + 4]);
                mma8(acc[nt][0], acc[nt][1], acc[nt][2], acc[nt][3], a0, a1, a2, a3, b0, b1);
            }
        }
    }

#pragma unroll
    for (int nt = 0; nt < 2; nt++) {
        int c0 = n0 + nw * 16 + nt * 8 + 2 * tig;
#pragma unroll
        for (int rr = 0; rr < 2; rr++) {
            int m = m0 + mw * 16 + grp + rr * 8;
            float2 qv = *(const float2*)&query[(size_t)m * Cc + c0];
            float2 ov;
            ov.x = acc[nt][rr * 2 + 0] + bias_s[c0 - n0]     + qv.x;
            ov.y = acc[nt][rr * 2 + 1] + bias_s[c0 - n0 + 1] + qv.y;
            *(float2*)&out[(size_t)m * Cc + c0] = ov;
        }
    }
}

// ---------------------------------------------------------------------------
extern "C" void kernel_launch(void* const* d_in, const int* in_sizes, int n_in,
                              void* d_out, int out_size)
{
    const float* query = (const float*)d_in[0];
    const float* mask  = (const float*)d_in[1];
    const float* Wq = (const float*)d_in[2];
    const float* bq = (const float*)d_in[3];
    const float* Wk = (const float*)d_in[4];
    const float* bk = (const float*)d_in[5];
    const float* Wv = (const float*)d_in[6];
    const float* bv = (const float*)d_in[7];
    const float* Wo = (const float*)d_in[8];
    const float* bo = (const float*)d_in[9];

    float* out_query = (float*)d_out;                       // [B,N,C]
    float* vis       = out_query + (size_t)Bc * Nc * Cc;    // [B,H,N,N]

    dim3 gr(Nc / 256, Nc / 256, Bc);
    rmax_kernel<<<gr, 256>>>(mask);

    dim3 gt(Nc / 64, Nc / 64, Bc);
    maskt_kernel<<<gt, 256>>>(mask);

    dim3 gq((Bc * Nc) / 32, Cc / 64, 3);
    qkv_mma_kernel<<<gq, 256>>>(query, Wq, Wk, Wv, bq, bk, bv);

    // smem: lg 131584 + Qsh 1280 + stage 40960 + red 1088 = 174,912 B
    size_t smem = (size_t)(16 * LGS * 4 + 16 * KSS * 2 + 40960 + 272 * 4);
    cudaFuncSetAttribute(attn_kernel, cudaFuncAttributeMaxDynamicSharedMemorySize, (int)smem);
    dim3 ga(Hc, Nc / 16, Bc);   // h fastest -> mt rows shared in L2
    attn_kernel<<<ga, 512, smem>>>(mask, vis);

    dim3 go((Bc * Nc) / 32, Cc / 64);
    oproj_mma_kernel<<<go, 256>>>(Wo, bo, query, out_query);
}